// round 2
// baseline (speedup 1.0000x reference)
#include <cuda_runtime.h>

#define BB 16
#define EE 128
#define CC 512
#define NCL 5
#define KITERS 12

// ---------------- device scratch (no allocations allowed) ----------------
__device__ float  g_sqdist[BB*EE*EE];   // later overwritten in-place with W
__device__ float  g_norm[BB*EE];
__device__ double g_psum[256];
__device__ double g_psq[256];
__device__ float  g_rowsum[BB*EE];
__device__ int    g_lbl64;              // 1 if labels buffer is int64

// ---------------- f32x2 packed helpers (Blackwell) ----------------
__device__ __forceinline__ unsigned long long pk2(float a, float b) {
    unsigned long long r;
    asm("mov.b64 %0, {%1,%2};" : "=l"(r) : "f"(a), "f"(b));
    return r;
}
__device__ __forceinline__ void unpk2(unsigned long long v, float& lo, float& hi) {
    asm("mov.b64 {%0,%1}, %2;" : "=f"(lo), "=f"(hi) : "l"(v));
}
__device__ __forceinline__ void fma2(unsigned long long& acc,
                                     unsigned long long a, unsigned long long b) {
    asm("fma.rn.f32x2 %0, %1, %2, %0;" : "+l"(acc) : "l"(a), "l"(b));
}
__device__ __forceinline__ unsigned long long add2(unsigned long long a,
                                                   unsigned long long b) {
    unsigned long long r;
    asm("add.rn.f32x2 %0, %1, %2;" : "=l"(r) : "l"(a), "l"(b));
    return r;
}

// ================= K0: row norms + labels dtype detection =================
// grid 256, block 256 (8 warps -> 8 rows each)
__global__ void k_norm(const float* __restrict__ x, const int* __restrict__ lab32) {
    int t = threadIdx.x;
    if (blockIdx.x == 0) {
        // int64 labels (values 0..5, little-endian) => odd 32-bit words are 0.
        // Scan first 1024 odd words (in-bounds for both dtypes).
        __shared__ int sflag;
        if (t == 0) sflag = 0;
        __syncthreads();
        int v = 0;
        #pragma unroll
        for (int k = 0; k < 4; k++) v |= lab32[2*(t + 256*k) + 1];
        if (v) sflag = 1;
        __syncthreads();
        if (t == 0) g_lbl64 = (sflag == 0);
    }
    int r    = blockIdx.x * 8 + (t >> 5);
    int lane = t & 31;
    const float* row = x + (size_t)r * CC;
    float s = 0.f;
    #pragma unroll
    for (int k = 0; k < 16; k++) { float v = row[lane + 32*k]; s += v * v; }
    #pragma unroll
    for (int o = 16; o; o >>= 1) s += __shfl_xor_sync(0xffffffffu, s, o);
    if (lane == 0) g_norm[r] = s;
}

// ================= K1: Gram -> sq_dist + stats partials =================
// grid (4,4,16): (j-tile, i-tile, batch). block 256 = 16x16, each thread 2x2.
__global__ void k_gram(const float* __restrict__ x) {
    __shared__ float XI[32][65];
    __shared__ float XJ[32][65];
    __shared__ double red[256];
    int b  = blockIdx.z;
    int ib = blockIdx.y * 32, jb = blockIdx.x * 32;
    int t  = threadIdx.x;
    int tx = t & 15, ty = t >> 4;
    const float* xb = x + (size_t)b * EE * CC;

    float a00 = 0.f, a01 = 0.f, a10 = 0.f, a11 = 0.f;
    for (int kc = 0; kc < CC; kc += 64) {
        #pragma unroll
        for (int rr = 0; rr < 8; rr++) {
            int lin = t + rr * 256;
            int row = lin >> 6, cc = lin & 63;
            XI[row][cc] = xb[(ib + row) * CC + kc + cc];
            XJ[row][cc] = xb[(jb + row) * CC + kc + cc];
        }
        __syncthreads();
        #pragma unroll
        for (int cc = 0; cc < 64; cc++) {
            float ai0 = XI[2*ty][cc],  ai1 = XI[2*ty + 1][cc];
            float bj0 = XJ[2*tx][cc],  bj1 = XJ[2*tx + 1][cc];
            a00 += ai0 * bj0;  a01 += ai0 * bj1;
            a10 += ai1 * bj0;  a11 += ai1 * bj1;
        }
        __syncthreads();
    }

    const float rsc = 0.04419417382415922f;   // 1/sqrt(512)
    int gi = ib + 2*ty, gj = jb + 2*tx;
    float ni0 = g_norm[b*EE + gi],     ni1 = g_norm[b*EE + gi + 1];
    float nj0 = g_norm[b*EE + gj],     nj1 = g_norm[b*EE + gj + 1];
    float s00 = (ni0 + nj0 - 2.f*a00) * rsc;
    float s01 = (ni0 + nj1 - 2.f*a01) * rsc;
    float s10 = (ni1 + nj0 - 2.f*a10) * rsc;
    float s11 = (ni1 + nj1 - 2.f*a11) * rsc;
    float* o = g_sqdist + (size_t)(b*EE + gi) * EE + gj;
    o[0] = s00; o[1] = s01; o[EE] = s10; o[EE + 1] = s11;

    // masked stats (mask == off-diagonal); diag hits only s00/s11 (gi==gj)
    double d0 = s00, d1 = s01, d2 = s10, d3 = s11;
    double sm, sq;
    if (gi != gj) { sm = d0 + d1 + d2 + d3; sq = d0*d0 + d1*d1 + d2*d2 + d3*d3; }
    else          { sm = d1 + d2;           sq = d1*d1 + d2*d2; }

    red[t] = sm; __syncthreads();
    for (int o2 = 128; o2; o2 >>= 1) { if (t < o2) red[t] += red[t + o2]; __syncthreads(); }
    int pidx = b * 16 + blockIdx.y * 4 + blockIdx.x;
    if (t == 0) g_psum[pidx] = red[0];
    __syncthreads();
    red[t] = sq; __syncthreads();
    for (int o2 = 128; o2; o2 >>= 1) { if (t < o2) red[t] += red[t + o2]; __syncthreads(); }
    if (t == 0) g_psq[pidx] = red[0];
}

// ================= K2: weights (in-place) + row sums =================
// grid (16 rowgroups, 16 batches), block 256 = 8 warps = 8 rows
__global__ void k_weights() {
    __shared__ double red[256];
    __shared__ float sh_inv;
    int t = threadIdx.x;

    red[t] = g_psum[t]; __syncthreads();
    for (int o = 128; o; o >>= 1) { if (t < o) red[t] += red[t + o]; __syncthreads(); }
    double S1 = red[0];
    __syncthreads();
    red[t] = g_psq[t]; __syncthreads();
    for (int o = 128; o; o >>= 1) { if (t < o) red[t] += red[t + o]; __syncthreads(); }
    if (t == 0) {
        double S2  = red[0];
        const double cnt = (double)BB * EE * (EE - 1);   // mask = off-diagonal
        double var = (S2 - S1 * S1 / cnt) / (cnt - 1.0); // Bessel (ddof=1)
        sh_inv = (float)(1.0 / sqrt(var));
    }
    __syncthreads();
    float inv = sh_inv;

    int b    = blockIdx.y;
    int i    = blockIdx.x * 8 + (t >> 5);
    int lane = t & 31;
    float rs = 0.f;
    float* rowp = g_sqdist + (size_t)(b*EE + i) * EE;
    #pragma unroll
    for (int k = 0; k < 4; k++) {
        int j = lane + 32*k;
        float w = (j == i) ? 0.f : expf(-rowp[j] * inv);
        rowp[j] = w;
        rs += w;
    }
    #pragma unroll
    for (int o = 16; o; o >>= 1) rs += __shfl_xor_sync(0xffffffffu, rs, o);
    if (lane == 0) g_rowsum[b*EE + i] = rs;
}

// ================= K3: Neumann propagation + output =================
// grid 16 (one batch per block), block 256: thread = (row i, j-half)
// P = (I - aS)^-1 = sum_k (aS)^k ; apply to [onehot(5) | ones] -> y and L1 norm.
// S row held in registers; W symmetric => coalesced loads of W's columns.
__global__ void k_prop(const int* __restrict__ lab32, float* __restrict__ out) {
    __shared__ float f[EE];
    __shared__ __align__(16) float v[EE * 8];
    __shared__ __align__(16) float pbuf[EE * 8];
    int b = blockIdx.x, t = threadIdx.x;
    int i = t & 127, half = t >> 7;
    int base = half * 64;

    if (t < EE) f[t] = 0.2f / (1e-4f + g_rowsum[b*EE + t]);   // alpha folded in
    __syncthreads();

    // s[jj] = alpha * S[i][base+jj] = W[base+jj][i] * f[base+jj]   (W symmetric)
    const float* Wb = g_sqdist + (size_t)b * EE * EE;
    float s[64];
    #pragma unroll
    for (int jj = 0; jj < 64; jj++)
        s[jj] = Wb[(base + jj) * EE + i] * f[base + jj];

    unsigned long long a01 = 0ull, a23 = 0ull, a45 = 0ull;
    if (t < EE) {
        int lbl = g_lbl64 ? lab32[2*(b*EE + t)] : lab32[b*EE + t];
        float vv[6];
        #pragma unroll
        for (int c = 0; c < NCL; c++) vv[c] = (lbl == c) ? 1.f : 0.f;
        vv[5] = 1.f;   // ones column -> L1 row norm of P (P >= 0)
        #pragma unroll
        for (int c = 0; c < 6; c++) v[t*8 + c] = vv[c];
        v[t*8 + 6] = 0.f; v[t*8 + 7] = 0.f;
        a01 = pk2(vv[0], vv[1]); a23 = pk2(vv[2], vv[3]); a45 = pk2(vv[4], vv[5]);
    }
    __syncthreads();

    for (int it = 0; it < KITERS; it++) {
        unsigned long long p01 = 0ull, p23 = 0ull, p45 = 0ull;
        #pragma unroll
        for (int jj = 0; jj < 64; jj++) {
            int j = base + jj;
            unsigned long long ss = pk2(s[jj], s[jj]);
            ulonglong2 w = *(const ulonglong2*)&v[j*8];
            unsigned long long w2 = *(const unsigned long long*)&v[j*8 + 4];
            fma2(p01, ss, w.x); fma2(p23, ss, w.y); fma2(p45, ss, w2);
        }
        if (half) {
            *(ulonglong2*)&pbuf[i*8] = make_ulonglong2(p01, p23);
            *(unsigned long long*)&pbuf[i*8 + 4] = p45;
        }
        __syncthreads();
        if (!half) {
            ulonglong2 q = *(const ulonglong2*)&pbuf[i*8];
            unsigned long long q2 = *(const unsigned long long*)&pbuf[i*8 + 4];
            p01 = add2(p01, q.x); p23 = add2(p23, q.y); p45 = add2(p45, q2);
            a01 = add2(a01, p01); a23 = add2(a23, p23); a45 = add2(a45, p45);
            *(ulonglong2*)&v[i*8] = make_ulonglong2(p01, p23);
            *(unsigned long long*)&v[i*8 + 4] = p45;
        }
        __syncthreads();   // v fully updated before next iteration reads it
    }

    if (!half) {
        float y0, y1, y2, y3, y4, l1;
        unpk2(a01, y0, y1); unpk2(a23, y2, y3); unpk2(a45, y4, l1);
        float inv = 1.f / fmaxf(l1, 1e-12f);
        float* o = out + (size_t)(b*EE + i) * NCL;
        o[0] = logf(y0 * inv + 1e-6f);
        o[1] = logf(y1 * inv + 1e-6f);
        o[2] = logf(y2 * inv + 1e-6f);
        o[3] = logf(y3 * inv + 1e-6f);
        o[4] = logf(y4 * inv + 1e-6f);
    }
}

// ================= launcher =================
extern "C" void kernel_launch(void* const* d_in, const int* in_sizes, int n_in,
                              void* d_out, int out_size) {
    const float* x   = (const float*)d_in[0];
    const int*   lab = (const int*)d_in[1];   // int32 or int64 — detected on device
    float*       out = (float*)d_out;

    k_norm<<<256, 256>>>(x, lab);
    k_gram<<<dim3(4, 4, BB), 256>>>(x);
    k_weights<<<dim3(16, BB), 256>>>();
    k_prop<<<BB, 256>>>(lab, out);
}